// round 15
// baseline (speedup 1.0000x reference)
#include <cuda_runtime.h>
#include <cstdint>

// MaxFeatBlockDescriptorLayer, fused single launch (R13 + dedicated gatherers):
//   Blocks [0,64): producers. Block (b,chunk) reduces 512 positions x 8
//   classes of prob (2 pos/thread local pair reduce; per class redux.max on
//   float bits + redux.max on complemented index among candidates = exact
//   first-index; fixed-point redux.add for the sum). 8x8 smem combine
//   (redux, mask 0xff), publish ONE 16B slot per (b,class,chunk) via
//   st.global.cg.v4 {comp idx, val bits, fixed sum, flag}.
//   Blocks [64,80): gatherers, one per (b,k). ALL 8 warps poll the 32 slots
//   redundantly from launch (1/lane, nanosleep backoff, memory-clobbered
//   .cg ops -- loads already in flight when the last producer publishes),
//   redux-reduce so every thread holds arg/mask in registers -> emb loads
//   issue immediately; slot reset deferred under emb load latency
//   (sole reader -> replay-safe).
//
// Exactness: argmax identical to jnp.argmax (first index). Mask uses a
// fixed-point sum (error ~1e-5 rel, cannot flip mean~0.5 vs tau=0.3).

#define N_POS    16384
#define N_CLS    8
#define C_DIM    2048
#define CHUNKS   32
#define POS_PC   (N_POS / CHUNKS)        // 512
#define NTHREADS 256
#define MAX_B    8
// mask threshold: sum_fixed > 0.3 * 16384 * 65536
#define TAU_FIXED 322122547u

// 16B slot: .x = comp idx, .y = val bits, .z = fixed sum, .w = flag
__device__ uint4 g_slot[MAX_B * N_CLS * CHUNKS];

__device__ __forceinline__ void slot_store(uint4* p, uint4 v) {
    asm volatile("st.global.cg.v4.u32 [%0], {%1,%2,%3,%4};"
                 :: "l"(p), "r"(v.x), "r"(v.y), "r"(v.z), "r"(v.w)
                 : "memory");
}
__device__ __forceinline__ uint4 slot_load(const uint4* p) {
    uint4 r;
    asm volatile("ld.global.cg.v4.u32 {%0,%1,%2,%3}, [%4];"
                 : "=r"(r.x), "=r"(r.y), "=r"(r.z), "=r"(r.w)
                 : "l"(p) : "memory");
    return r;
}
__device__ __forceinline__ unsigned redux_max(unsigned v, unsigned mask) {
    unsigned d;
    asm volatile("redux.sync.max.u32 %0, %1, %2;" : "=r"(d) : "r"(v), "r"(mask));
    return d;
}
__device__ __forceinline__ unsigned redux_add(unsigned v, unsigned mask) {
    unsigned d;
    asm volatile("redux.sync.add.u32 %0, %1, %2;" : "=r"(d) : "r"(v), "r"(mask));
    return d;
}

__global__ __launch_bounds__(NTHREADS)
void mfbd_fused(const float* __restrict__ emb,
                const float* __restrict__ prob,
                float* __restrict__ out,
                int nprod)
{
    const int t    = threadIdx.x;
    const int w    = t >> 5;
    const int lane = t & 31;

    __shared__ unsigned s_hi[N_CLS][N_CLS];
    __shared__ unsigned s_lo[N_CLS][N_CLS];
    __shared__ unsigned s_fx[N_CLS][N_CLS];

    if (blockIdx.x < (unsigned)nprod) {
        // ======================= PRODUCER =======================
        const int b     = blockIdx.x / CHUNKS;
        const int chunk = blockIdx.x % CHUNKS;

        const float4* __restrict__ p4 =
            (const float4*)(prob + ((size_t)b * N_POS + (size_t)chunk * POS_PC) * N_CLS);
        const float4 a0 = __ldg(p4 + 4 * t);
        const float4 a1 = __ldg(p4 + 4 * t + 1);
        const float4 b0 = __ldg(p4 + 4 * t + 2);
        const float4 b1 = __ldg(p4 + 4 * t + 3);
        const float va[8] = { a0.x, a0.y, a0.z, a0.w, a1.x, a1.y, a1.z, a1.w };
        const float vb[8] = { b0.x, b0.y, b0.z, b0.w, b1.x, b1.y, b1.z, b1.w };

        const int pos0 = chunk * POS_PC + 2 * t;

        unsigned hi8[8], lo8[8], fx8[8];
        #pragma unroll
        for (int c = 0; c < N_CLS; ++c) {
            const float    vm   = fmaxf(va[c], vb[c]);
            const unsigned off  = (vb[c] > va[c]) ? 1u : 0u;   // tie -> earlier
            const unsigned bits = __float_as_uint(vm);
            const unsigned comp = (unsigned)(N_POS - 1 - (pos0 + (int)off));
            const unsigned sfx  = (unsigned)__float2uint_rn((va[c] + vb[c]) * 65536.0f);

            const unsigned mx   = redux_max(bits, 0xffffffffu);
            const unsigned cand = (bits == mx) ? comp : 0u;
            hi8[c] = mx;
            lo8[c] = redux_max(cand, 0xffffffffu);   // largest comp = first idx
            fx8[c] = redux_add(sfx, 0xffffffffu);
        }
        if (lane < N_CLS) {
            s_hi[w][lane] = hi8[lane];
            s_lo[w][lane] = lo8[lane];
            s_fx[w][lane] = fx8[lane];
        }
        __syncthreads();

        // combine 8 warp-partials per class: warp w -> class w, lanes 0..7
        if (lane < N_CLS) {
            const unsigned hi = s_hi[lane][w];
            const unsigned lo = s_lo[lane][w];
            const unsigned fx = s_fx[lane][w];
            const unsigned mx   = redux_max(hi, 0xffu);
            const unsigned cand = (hi == mx) ? lo : 0u;
            const unsigned mlo  = redux_max(cand, 0xffu);
            const unsigned sfx  = redux_add(fx, 0xffu);
            if (lane == 0) {
                uint4 sl;
                sl.x = mlo;
                sl.y = mx;
                sl.z = sfx;
                sl.w = 1u;                            // flag
                slot_store(&g_slot[(b * N_CLS + w) * CHUNKS + chunk], sl);
            }
        }
        return;
    }

    // ======================= GATHERER (polls from launch) =======================
    const int gid = blockIdx.x - nprod;
    const int b = gid / N_CLS;
    const int k = gid % N_CLS;

    uint4* const base = &g_slot[(b * N_CLS + k) * CHUNKS];

    // ALL warps poll redundantly: 32 slots, 1 per lane.
    uint4 r0;
    for (;;) {
        r0 = slot_load(base + lane);
        if (__all_sync(0xffffffffu, r0.w != 0u)) break;
        __nanosleep(32);
    }
    // redux reduce -> every lane ends with the final arg/mask.
    const unsigned mx   = redux_max(r0.y, 0xffffffffu);
    const unsigned cand = (r0.y == mx) ? r0.x : 0u;
    const unsigned mlo  = redux_max(cand, 0xffffffffu);
    const unsigned tot  = redux_add(r0.z, 0xffffffffu);

    const int   arg  = N_POS - 1 - (int)mlo;
    const float mask = (tot > TAU_FIXED) ? 1.0f : 0.0f;

    // Issue emb loads immediately (critical path).
    const float4* __restrict__ src =
        (const float4*)(emb + ((size_t)b * N_POS + (size_t)arg) * C_DIM);
    float4* __restrict__ dst =
        (float4*)(out + ((size_t)b * N_CLS + (size_t)k) * C_DIM);

    float4 v0 = __ldg(src + t);
    float4 v1 = __ldg(src + t + NTHREADS);

    // Reset own slots off the critical path (hidden under emb load latency).
    __syncthreads();
    if (w == 0) slot_store(base + lane, make_uint4(0u, 0u, 0u, 0u));

    v0.x *= mask; v0.y *= mask; v0.z *= mask; v0.w *= mask;
    v1.x *= mask; v1.y *= mask; v1.z *= mask; v1.w *= mask;
    dst[t]            = v0;
    dst[t + NTHREADS] = v1;
}

extern "C" void kernel_launch(void* const* d_in, const int* in_sizes, int n_in,
                              void* d_out, int out_size)
{
    const float* emb  = (const float*)d_in[0];
    const float* prob = (const float*)d_in[1];
    float* out = (float*)d_out;

    const int B = in_sizes[0] / (N_POS * C_DIM);   // = 2
    const int nprod = B * CHUNKS;                  // 64 producers
    const int grid  = nprod + B * N_CLS;           // +16 gatherers = 80 (1 wave)

    mfbd_fused<<<grid, NTHREADS>>>(emb, prob, out, nprod);
}

// round 16
// speedup vs baseline: 1.0337x; 1.0337x over previous
#include <cuda_runtime.h>
#include <cstdint>

// MaxFeatBlockDescriptorLayer, fused single launch (R13 redux + R7 grid):
//   128 blocks x 256 threads; block (b,chunk) reduces 256 positions x 8
//   classes of prob (1 pos/thread -> 16KB/block, half the L1-return
//   serialization of R13's 32KB). Per class: redux.max on float bits +
//   redux.max on complemented index among candidates (exact first-index),
//   fixed-point redux.add for the sum. Stage-2 combine via ONE uint4 smem
//   slot per (srcwarp,class) (conflict-free STS.128), publish ONE 16B slot
//   per (b,class,chunk) via st.global.cg.v4 {comp idx, val bits, sum, flag}.
//   Blocks with chunk<8 also gather (class k = chunk): ALL 8 warps poll the
//   64 slots redundantly (2/lane, nanosleep 16, memory-clobbered .cg ops),
//   pair-combine + redux so every thread holds arg/mask in registers -> emb
//   loads issue immediately; slot reset deferred under emb load latency.
//
// Exactness: argmax identical to jnp.argmax (first index). Mask uses a
// fixed-point sum (error ~1e-5 rel, cannot flip mean~0.5 vs tau=0.3).

#define N_POS    16384
#define N_CLS    8
#define C_DIM    2048
#define CHUNKS   64
#define POS_PC   (N_POS / CHUNKS)        // 256
#define NTHREADS 256
#define MAX_B    8
// mask threshold: sum_fixed > 0.3 * 16384 * 65536
#define TAU_FIXED 322122547u

// 16B slot: .x = comp idx, .y = val bits, .z = fixed sum, .w = flag
__device__ uint4 g_slot[MAX_B * N_CLS * CHUNKS];

__device__ __forceinline__ void slot_store(uint4* p, uint4 v) {
    asm volatile("st.global.cg.v4.u32 [%0], {%1,%2,%3,%4};"
                 :: "l"(p), "r"(v.x), "r"(v.y), "r"(v.z), "r"(v.w)
                 : "memory");
}
__device__ __forceinline__ uint4 slot_load(const uint4* p) {
    uint4 r;
    asm volatile("ld.global.cg.v4.u32 {%0,%1,%2,%3}, [%4];"
                 : "=r"(r.x), "=r"(r.y), "=r"(r.z), "=r"(r.w)
                 : "l"(p) : "memory");
    return r;
}
__device__ __forceinline__ unsigned redux_max(unsigned v, unsigned mask) {
    unsigned d;
    asm volatile("redux.sync.max.u32 %0, %1, %2;" : "=r"(d) : "r"(v), "r"(mask));
    return d;
}
__device__ __forceinline__ unsigned redux_add(unsigned v, unsigned mask) {
    unsigned d;
    asm volatile("redux.sync.add.u32 %0, %1, %2;" : "=r"(d) : "r"(v), "r"(mask));
    return d;
}

__global__ __launch_bounds__(NTHREADS)
void mfbd_fused(const float* __restrict__ emb,
                const float* __restrict__ prob,
                float* __restrict__ out)
{
    const int t    = threadIdx.x;
    const int w    = t >> 5;
    const int lane = t & 31;

    const int b     = blockIdx.x / CHUNKS;
    const int chunk = blockIdx.x % CHUNKS;

    // [srcwarp][class]: STS.128 conflict-free (lane*16B stride)
    __shared__ uint4 s_c[N_CLS][N_CLS];

    // ------------- Producer: 1 position/thread, regs only -------------
    const float4* __restrict__ p4 =
        (const float4*)(prob + ((size_t)b * N_POS + (size_t)chunk * POS_PC) * N_CLS);
    const float4 a0 = __ldg(p4 + 2 * t);
    const float4 a1 = __ldg(p4 + 2 * t + 1);
    const float v[8] = { a0.x, a0.y, a0.z, a0.w, a1.x, a1.y, a1.z, a1.w };

    const unsigned comp = (unsigned)(N_POS - 1 - (chunk * POS_PC + t));

    unsigned hi8[8], lo8[8], fx8[8];
    #pragma unroll
    for (int c = 0; c < N_CLS; ++c) {
        const unsigned bits = __float_as_uint(v[c]);
        const unsigned sfx  = (unsigned)__float2uint_rn(v[c] * 65536.0f);

        const unsigned mx   = redux_max(bits, 0xffffffffu);
        const unsigned cand = (bits == mx) ? comp : 0u;   // largest comp = first idx
        hi8[c] = mx;
        lo8[c] = redux_max(cand, 0xffffffffu);
        fx8[c] = redux_add(sfx, 0xffffffffu);
    }
    if (lane < N_CLS) {     // lane c writes class c partial: one STS.128
        s_c[w][lane] = make_uint4(lo8[lane], hi8[lane], fx8[lane], 0u);
    }
    __syncthreads();

    // ---- combine 8 warp-partials per class: warp w -> class w, lanes 0..7 ----
    if (lane < N_CLS) {
        const uint4 p = s_c[lane][w];        // [srcwarp=lane][class=w]
        const unsigned mx   = redux_max(p.y, 0xffu);
        const unsigned cand = (p.y == mx) ? p.x : 0u;
        const unsigned mlo  = redux_max(cand, 0xffu);
        const unsigned sfx  = redux_add(p.z, 0xffu);
        if (lane == 0) {
            slot_store(&g_slot[(b * N_CLS + w) * CHUNKS + chunk],
                       make_uint4(mlo, mx, sfx, 1u));
        }
    }

    // ------------- Gather blocks: chunk < 8 -> class k = chunk -------------
    if (chunk >= N_CLS) return;
    const int k = chunk;

    uint4* const base = &g_slot[(b * N_CLS + k) * CHUNKS];

    // ALL warps poll redundantly: 64 slots, 2 per lane (MLP=2).
    uint4 r0, r1;
    for (;;) {
        r0 = slot_load(base + lane);
        r1 = slot_load(base + lane + 32);
        if (__all_sync(0xffffffffu, (r0.w & r1.w) != 0u)) break;
        __nanosleep(16);
    }
    // pair combine (exact first-index semantics), then redux broadcast
    unsigned hi = r0.y > r1.y ? r0.y : r1.y;
    unsigned c0 = (r0.y == hi) ? r0.x : 0u;
    unsigned c1 = (r1.y == hi) ? r1.x : 0u;
    unsigned lo = c0 > c1 ? c0 : c1;
    unsigned fx = r0.z + r1.z;

    const unsigned mx   = redux_max(hi, 0xffffffffu);
    const unsigned cand = (hi == mx) ? lo : 0u;
    const unsigned mlo  = redux_max(cand, 0xffffffffu);
    const unsigned tot  = redux_add(fx, 0xffffffffu);

    const int   arg  = N_POS - 1 - (int)mlo;
    const float mask = (tot > TAU_FIXED) ? 1.0f : 0.0f;

    // Issue emb loads immediately (critical path).
    const float4* __restrict__ src =
        (const float4*)(emb + ((size_t)b * N_POS + (size_t)arg) * C_DIM);
    float4* __restrict__ dst =
        (float4*)(out + ((size_t)b * N_CLS + (size_t)k) * C_DIM);

    float4 v0 = __ldg(src + t);
    float4 v1 = __ldg(src + t + NTHREADS);

    // Reset own slots off the critical path (hidden under emb load latency).
    __syncthreads();
    if (w == 0) {
        slot_store(base + lane,      make_uint4(0u, 0u, 0u, 0u));
        slot_store(base + lane + 32, make_uint4(0u, 0u, 0u, 0u));
    }

    v0.x *= mask; v0.y *= mask; v0.z *= mask; v0.w *= mask;
    v1.x *= mask; v1.y *= mask; v1.z *= mask; v1.w *= mask;
    dst[t]            = v0;
    dst[t + NTHREADS] = v1;
}

extern "C" void kernel_launch(void* const* d_in, const int* in_sizes, int n_in,
                              void* d_out, int out_size)
{
    const float* emb  = (const float*)d_in[0];
    const float* prob = (const float*)d_in[1];
    float* out = (float*)d_out;

    const int B = in_sizes[0] / (N_POS * C_DIM);   // = 2

    mfbd_fused<<<B * CHUNKS, NTHREADS>>>(emb, prob, out);   // 128 blocks, 1 wave
}